// round 16
// baseline (speedup 1.0000x reference)
#include <cuda_runtime.h>
#include <cuda_fp16.h>
#include <cstdint>
#include <cstddef>

#define EMB   2048
#define BATCH 2
#define SEQ   2048
#define NHEAD 16
#define HDIM  128
#define LAT   512
#define MTOT  (BATCH*SEQ)   // 4096

// fp16 copies of inputs (converted once per run) + fp16 intermediates.
__device__ __half g_xh [(size_t)MTOT*EMB];
__device__ __half g_wq [(size_t)EMB*EMB];
__device__ __half g_wd [(size_t)LAT*EMB];
__device__ __half g_wk [(size_t)EMB*LAT];
__device__ __half g_wv [(size_t)EMB*LAT];
__device__ __half g_wo [(size_t)EMB*EMB];
__device__ __half g_lath[(size_t)MTOT*LAT];
__device__ __half g_qh [(size_t)MTOT*EMB];
__device__ __half g_kh [(size_t)MTOT*EMB];
__device__ __half g_vh [(size_t)MTOT*EMB];
__device__ __half g_ctxh[(size_t)MTOT*EMB];

__device__ __forceinline__ uint32_t f2h2(float lo, float hi) {
    uint32_t r;
    asm("cvt.rn.f16x2.f32 %0, %1, %2;" : "=r"(r) : "f"(hi), "f"(lo));
    return r;
}
__device__ __forceinline__ float ex2f(float x) {
    float r;
    asm("ex2.approx.ftz.f32 %0, %1;" : "=f"(r) : "f"(x));
    return r;
}
__device__ __forceinline__ void mma_f16(float d[4],
                                        uint32_t a0, uint32_t a1, uint32_t a2, uint32_t a3,
                                        uint32_t b0, uint32_t b1) {
    asm volatile(
        "mma.sync.aligned.m16n8k16.row.col.f32.f16.f16.f32 "
        "{%0,%1,%2,%3}, {%4,%5,%6,%7}, {%8,%9}, {%0,%1,%2,%3};"
        : "+f"(d[0]), "+f"(d[1]), "+f"(d[2]), "+f"(d[3])
        : "r"(a0), "r"(a1), "r"(a2), "r"(a3), "r"(b0), "r"(b1));
}
__device__ __forceinline__ void ldsm4(uint32_t r[4], uint32_t addr) {
    asm volatile("ldmatrix.sync.aligned.m8n8.x4.shared.b16 {%0,%1,%2,%3}, [%4];"
        : "=r"(r[0]), "=r"(r[1]), "=r"(r[2]), "=r"(r[3]) : "r"(addr));
}
__device__ __forceinline__ void ldsm4t(uint32_t r[4], uint32_t addr) {
    asm volatile("ldmatrix.sync.aligned.m8n8.x4.trans.shared.b16 {%0,%1,%2,%3}, [%4];"
        : "=r"(r[0]), "=r"(r[1]), "=r"(r[2]), "=r"(r[3]) : "r"(addr));
}
__device__ __forceinline__ void cpa16(uint32_t dst, const void* src) {
    asm volatile("cp.async.cg.shared.global [%0], [%1], 16;" :: "r"(dst), "l"(src));
}
__device__ __forceinline__ void cpa_commit() {
    asm volatile("cp.async.commit_group;" ::: "memory");
}
__device__ __forceinline__ void cpa_wait0() {
    asm volatile("cp.async.wait_group 0;" ::: "memory");
}

// ---------------------------------------------------------------------------
// cvt6: fp32 -> fp16 for x + 5 weight tensors, one launch (grid.y selects).
// ---------------------------------------------------------------------------
__global__ void cvt6(const float* s0, const float* s1, const float* s2,
                     const float* s3, const float* s4, const float* s5,
                     __half* d0, __half* d1, __half* d2,
                     __half* d3, __half* d4, __half* d5,
                     int n0, int n1, int n2, int n3, int n4, int n5) {
    const float* s; __half* d; int n;
    switch (blockIdx.y) {
        case 0:  s = s0; d = d0; n = n0; break;
        case 1:  s = s1; d = d1; n = n1; break;
        case 2:  s = s2; d = d2; n = n2; break;
        case 3:  s = s3; d = d3; n = n3; break;
        case 4:  s = s4; d = d4; n = n4; break;
        default: s = s5; d = d5; n = n5; break;
    }
    const int i = blockIdx.x * 256 + threadIdx.x;
    if (i * 4 < n) {
        const float4 v = ((const float4*)s)[i];
        ((uint2*)d)[i] = make_uint2(f2h2(v.x, v.y), f2h2(v.z, v.w));
    }
}

// ---------------------------------------------------------------------------
// GEMM v7 (fp16, 128x128x64 tiles, warp tile 64x64): C = A*B^T (+bias).
// 128 thr, 4 warps (2m x 2n), 2-stage cp.async, 2 blocks/SM.
// Per warp k16 step: 4 A-ldsm.x4 + 4 B-ldsm.x4 (4KB) -> 32 HMMA
//   => 128 B/HMMA crossbar (was 192), the measured binding term.
// Rows: 64 halves = 128B data, 144B stride (conflict-free cp.async + ldsm).
// ---------------------------------------------------------------------------
#define GBM 128
#define GBN 128
#define GBK 64
#define ROWB 144
#define ABUFW (128*36)               // words per A stage (18KB)
#define BBUFW (128*36)               // words per B stage (18KB)
#define BOFFW (2*ABUFW)
#define GEMM_SMEM ((2*ABUFW + 2*BBUFW) * 4)   // 73728 B

__global__ __launch_bounds__(128, 2)
void gemm_h_nt(const __half* __restrict__ A, const __half* __restrict__ B1,
               const __half* __restrict__ B2, const float* __restrict__ bias,
               void* __restrict__ C1v, void* __restrict__ C2v,
               int M, int N, int K, int cvt) {
    extern __shared__ uint32_t sm[];
    const uint32_t smem_u = (uint32_t)__cvta_generic_to_shared(sm);

    const __half* B = (blockIdx.z == 0) ? B1 : B2;
    void*         C = (blockIdx.z == 0) ? C1v : C2v;

    const int tid  = threadIdx.x;
    const int lane = tid & 31;
    const int wid  = tid >> 5;
    const int g    = lane >> 2;
    const int c    = lane & 3;
    const int wm   = (wid >> 1) * 64;    // 2 m-groups
    const int wn   = (wid & 1) * 64;     // 2 n-groups

    const int aRow = ((lane >> 3) & 1) * 8 + (lane & 7);
    const int aKB  = (lane >> 4) * 16;
    const int bRow = (lane >> 4) * 8 + (lane & 7);
    const int bKB  = ((lane >> 3) & 1) * 16;

    const int bm = blockIdx.y * GBM;
    const int bn = blockIdx.x * GBN;

    float acc[4][8][4];
#pragma unroll
    for (int i = 0; i < 4; i++)
#pragma unroll
        for (int j = 0; j < 8; j++)
#pragma unroll
            for (int r = 0; r < 4; r++) acc[i][j][r] = 0.f;

    auto loadTile = [&](int kt, int buf) {
#pragma unroll
        for (int i = 0; i < 8; i++) {           // A: 128 rows x 64 halves
            const int idx = tid + i * 128;
            const int r = idx >> 3, cs = idx & 7;
            cpa16(smem_u + buf * (ABUFW * 4) + r * ROWB + cs * 16,
                  A + (size_t)(bm + r) * K + kt * GBK + cs * 8);
        }
#pragma unroll
        for (int i = 0; i < 8; i++) {           // B: 128 rows x 64 halves
            const int idx = tid + i * 128;
            const int r = idx >> 3, cs = idx & 7;
            cpa16(smem_u + (BOFFW + buf * BBUFW) * 4 + r * ROWB + cs * 16,
                  B + (size_t)(bn + r) * K + kt * GBK + cs * 8);
        }
        cpa_commit();
    };

    const int ktiles = K / GBK;
    loadTile(0, 0);

    for (int kt = 0; kt < ktiles; kt++) {
        cpa_wait0();
        __syncthreads();
        if (kt + 1 < ktiles) loadTile(kt + 1, (kt + 1) & 1);

        const uint32_t Abase = smem_u + ((kt & 1) * ABUFW) * 4;
        const uint32_t Bbase = smem_u + (BOFFW + (kt & 1) * BBUFW) * 4;
#pragma unroll
        for (int s = 0; s < 4; s++) {           // four k16 steps per BK=64
            uint32_t afr[4][4], bfr[8][2];
#pragma unroll
            for (int mt = 0; mt < 4; mt++)
                ldsm4(afr[mt], Abase + (wm + mt * 16 + aRow) * ROWB + s * 32 + aKB);
#pragma unroll
            for (int j = 0; j < 4; j++) {
                uint32_t r4[4];
                ldsm4(r4, Bbase + (wn + j * 16 + bRow) * ROWB + s * 32 + bKB);
                bfr[2 * j][0]     = r4[0];
                bfr[2 * j][1]     = r4[1];
                bfr[2 * j + 1][0] = r4[2];
                bfr[2 * j + 1][1] = r4[3];
            }
#pragma unroll
            for (int mt = 0; mt < 4; mt++)
#pragma unroll
                for (int nt = 0; nt < 8; nt++)
                    mma_f16(acc[mt][nt], afr[mt][0], afr[mt][1], afr[mt][2], afr[mt][3],
                            bfr[nt][0], bfr[nt][1]);
        }
    }

#pragma unroll
    for (int mt = 0; mt < 4; mt++) {
        const int row0 = bm + wm + mt * 16 + g;
#pragma unroll
        for (int nt = 0; nt < 8; nt++) {
            const int col = bn + wn + nt * 8 + 2 * c;
            if (cvt) {
                __half* Ch = (__half*)C;
                *(uint32_t*)(Ch + (size_t)row0 * N + col) =
                    f2h2(acc[mt][nt][0], acc[mt][nt][1]);
                *(uint32_t*)(Ch + (size_t)(row0 + 8) * N + col) =
                    f2h2(acc[mt][nt][2], acc[mt][nt][3]);
            } else {
                float* Cf = (float*)C;
                float b0 = 0.f, b1 = 0.f;
                if (bias) { b0 = bias[col]; b1 = bias[col + 1]; }
                *(float2*)(Cf + (size_t)row0 * N + col) =
                    make_float2(acc[mt][nt][0] + b0, acc[mt][nt][1] + b1);
                *(float2*)(Cf + (size_t)(row0 + 8) * N + col) =
                    make_float2(acc[mt][nt][2] + b0, acc[mt][nt][3] + b1);
            }
        }
    }
}

// ---------------------------------------------------------------------------
// Flash attention v7 (R12-R14 body, ~178us): QT=64, KT=32, 256 thr,
// 2 blk/SM; fp16 mma + ldmatrix; no-max softmax; fp16 ctx output.
// ---------------------------------------------------------------------------
#define QROWB   272
#define KOFFB   17408
#define KSTGB   8704
#define VOFFB   34816
#define POFFW   13056
#define LOFFW   14336
#define FLASH_SMEM 57856

__global__ __launch_bounds__(256, 2)
void flash_attn(const __half* __restrict__ Qh, const __half* __restrict__ Kh,
                const __half* __restrict__ Vh, __half* __restrict__ Oh, int h0) {
    const int qb = gridDim.x - 1 - blockIdx.x;
    const int h  = h0 + blockIdx.y;
    const int b  = blockIdx.z;

    extern __shared__ uint32_t sm[];
    const uint32_t smem_u = (uint32_t)__cvta_generic_to_shared(sm);

    const int tid  = threadIdx.x;
    const int lane = tid & 31;
    const int w    = tid >> 5;
    const int g    = lane >> 2;
    const int c    = lane & 3;
    const int W    = w & 3;
    const int half = w >> 2;

    const size_t bh_off = ((size_t)b * SEQ) * EMB + (size_t)h * HDIM;

    const int lrow = (lane & 7) + ((lane >> 3) & 1) * 8;
    const int lkb  = (lane >> 4) * 16;

#pragma unroll
    for (int i = 0; i < 4; i++) {
        const int seg = tid + i * 256;
        const int r   = seg >> 4;
        const int cs  = seg & 15;
        cpa16(smem_u + r * QROWB + cs * 16,
              Qh + bh_off + (size_t)(qb * 64 + r) * EMB + cs * 8);
    }
    cpa_commit();

    auto loadKV = [&](int t) {
        const uint32_t kb = smem_u + KOFFB + (t & 1) * KSTGB;
        const uint32_t vb = smem_u + VOFFB + (t & 1) * KSTGB;
#pragma unroll
        for (int i = 0; i < 2; i++) {
            const int seg = tid + i * 256;
            const int r   = seg >> 4;
            const int cs  = seg & 15;
            const size_t go = bh_off + (size_t)(t * 32 + r) * EMB + cs * 8;
            cpa16(kb + r * QROWB + cs * 16, Kh + go);
            cpa16(vb + r * QROWB + cs * 16, Vh + go);
        }
        cpa_commit();
    };

    loadKV(0);

    float oacc[8][4];
#pragma unroll
    for (int i = 0; i < 8; i++)
#pragma unroll
        for (int j = 0; j < 4; j++) oacc[i][j] = 0.f;

    float lsum0 = 0.f, lsum1 = 0.f;
    const float sc2 = 0.08838834764831843f * 1.4426950408889634f;

    const int nkb   = 2 * qb + 2;
    const int kbmax = 2 * qb + (W >= 2 ? 1 : 0);
    const int row0  = qb * 64 + W * 16 + g;
    const int row1  = row0 + 8;

    const uint32_t Qbase = smem_u + (W * 16 + lrow) * QROWB + lkb;
    uint32_t* Pw = sm + POFFW;
    const int poff = 20 * (W * 16 + g) + c;

    for (int t = 0; t < nkb; t++) {
        cpa_wait0();
        __syncthreads();
        if (t + 1 < nkb) loadKV(t + 1);

        const bool active = (t <= kbmax);
        const uint32_t Kbase = smem_u + KOFFB + (t & 1) * KSTGB +
                               (half * 16 + lrow) * QROWB + lkb;
        const uint32_t Vbase = smem_u + VOFFB + (t & 1) * KSTGB +
                               lrow * QROWB + half * 128 + lkb;

        if (active) {
            float sacc[2][2][4];
#pragma unroll
            for (int s = 0; s < 2; s++)
#pragma unroll
                for (int nt = 0; nt < 2; nt++)
#pragma unroll
                    for (int j = 0; j < 4; j++) sacc[s][nt][j] = 0.f;

#pragma unroll
            for (int ks = 0; ks < 8; ks++) {
                uint32_t af[4], bf[4];
                ldsm4(af, Qbase + ks * 32);
                ldsm4(bf, Kbase + ks * 32);
                mma_f16(sacc[ks & 1][0], af[0], af[1], af[2], af[3], bf[0], bf[2]);
                mma_f16(sacc[ks & 1][1], af[0], af[1], af[2], af[3], bf[1], bf[3]);
            }

            const bool maskit = (t == kbmax);
            const int colbase = t * 32 + half * 16 + 2 * c;
#pragma unroll
            for (int nt = 0; nt < 2; nt++) {
                float s0 = (sacc[0][nt][0] + sacc[1][nt][0]) * sc2;
                float s1 = (sacc[0][nt][1] + sacc[1][nt][1]) * sc2;
                float s2 = (sacc[0][nt][2] + sacc[1][nt][2]) * sc2;
                float s3 = (sacc[0][nt][3] + sacc[1][nt][3]) * sc2;
                if (maskit) {
                    const int c0 = colbase + nt * 8, c1 = c0 + 1;
                    if (c0 > row0) s0 = -126.f;
                    if (c1 > row0) s1 = -126.f;
                    if (c0 > row1) s2 = -126.f;
                    if (c1 > row1) s3 = -126.f;
                }
                const float p0 = ex2f(s0), p1 = ex2f(s1);
                const float p2 = ex2f(s2), p3 = ex2f(s3);
                lsum0 += p0 + p1;
                lsum1 += p2 + p3;
                const int pw = 20 * (W * 16 + g) + 8 * half + 4 * nt + c;
                Pw[pw]       = f2h2(p0, p1);
                Pw[pw + 160] = f2h2(p2, p3);
            }
        }

        __syncthreads();

        if (active) {
#pragma unroll
            for (int s = 0; s < 2; s++) {
                const uint32_t a0 = Pw[poff + 8 * s];
                const uint32_t a1 = Pw[poff + 8 * s + 160];
                const uint32_t a2 = Pw[poff + 8 * s + 4];
                const uint32_t a3 = Pw[poff + 8 * s + 164];
#pragma unroll
                for (int j = 0; j < 4; j++) {
                    uint32_t vf[4];
                    ldsm4t(vf, Vbase + s * 16 * QROWB + j * 32);
                    mma_f16(oacc[2 * j],     a0, a1, a2, a3, vf[0], vf[1]);
                    mma_f16(oacc[2 * j + 1], a0, a1, a2, a3, vf[2], vf[3]);
                }
            }
        }
    }

#pragma unroll
    for (int msk = 1; msk < 4; msk <<= 1) {
        lsum0 += __shfl_xor_sync(0xffffffffu, lsum0, msk);
        lsum1 += __shfl_xor_sync(0xffffffffu, lsum1, msk);
    }
    float* fsm = (float*)sm;
    if (c == 0) {
        fsm[LOFFW + (W * 16 + g) * 2 + half]     = lsum0;
        fsm[LOFFW + (W * 16 + g + 8) * 2 + half] = lsum1;
    }
    __syncthreads();
    const float inv0 = 1.f / (fsm[LOFFW + (W * 16 + g) * 2] +
                              fsm[LOFFW + (W * 16 + g) * 2 + 1]);
    const float inv1 = 1.f / (fsm[LOFFW + (W * 16 + g + 8) * 2] +
                              fsm[LOFFW + (W * 16 + g + 8) * 2 + 1]);

    __half* Obase = Oh + bh_off + (size_t)(qb * 64 + W * 16) * EMB;
#pragma unroll
    for (int nt = 0; nt < 8; nt++) {
        const int col = half * 64 + nt * 8 + 2 * c;
        *(uint32_t*)(Obase + (size_t)g * EMB + col) =
            f2h2(oacc[nt][0] * inv0, oacc[nt][1] * inv0);
        *(uint32_t*)(Obase + (size_t)(g + 8) * EMB + col) =
            f2h2(oacc[nt][2] * inv1, oacc[nt][3] * inv1);
    }
}

// ---------------------------------------------------------------------------
// Launch: cvt(0), q(1), lat(2), kv(3), flash(4), out(5).
// With 2-launch harness prelude, ncu -s 5 profiles the kv-GEMM.
// ---------------------------------------------------------------------------
extern "C" void kernel_launch(void* const* d_in, const int* in_sizes, int n_in,
                              void* d_out, int out_size) {
    (void)in_sizes; (void)n_in; (void)out_size;
    const float* x      = (const float*)d_in[0];
    const float* w_q    = (const float*)d_in[1];
    const float* w_down = (const float*)d_in[2];
    const float* w_up_k = (const float*)d_in[3];
    const float* w_up_v = (const float*)d_in[4];
    const float* w_out  = (const float*)d_in[5];
    const float* b_out  = (const float*)d_in[6];
    float* out = (float*)d_out;

    void *pxh, *pwq, *pwd, *pwk, *pwv, *pwo, *plath, *pqh, *pkh, *pvh, *pctxh;
    cudaGetSymbolAddress(&pxh,  g_xh);
    cudaGetSymbolAddress(&pwq,  g_wq);
    cudaGetSymbolAddress(&pwd,  g_wd);
    cudaGetSymbolAddress(&pwk,  g_wk);
    cudaGetSymbolAddress(&pwv,  g_wv);
    cudaGetSymbolAddress(&pwo,  g_wo);
    cudaGetSymbolAddress(&plath, g_lath);
    cudaGetSymbolAddress(&pqh,  g_qh);
    cudaGetSymbolAddress(&pkh,  g_kh);
    cudaGetSymbolAddress(&pvh,  g_vh);
    cudaGetSymbolAddress(&pctxh, g_ctxh);

    cudaFuncSetAttribute(gemm_h_nt, cudaFuncAttributeMaxDynamicSharedMemorySize, GEMM_SMEM);
    cudaFuncSetAttribute(flash_attn, cudaFuncAttributeMaxDynamicSharedMemorySize, FLASH_SMEM);

    // 0: convert x + 5 weights to fp16 (one launch)
    const int nx = MTOT * EMB, nq = EMB * EMB, nd = LAT * EMB, nk = EMB * LAT;
    cvt6<<<dim3((nx / 4 + 255) / 256, 6), 256>>>(
        x, w_q, w_down, w_up_k, w_up_v, w_out,
        (__half*)pxh, (__half*)pwq, (__half*)pwd, (__half*)pwk, (__half*)pwv, (__half*)pwo,
        nx, nq, nd, nk, nk, nq);
    // 1: q = xh @ wq^T (f16 out)
    gemm_h_nt<<<dim3(EMB / GBN, MTOT / GBM, 1), 128, GEMM_SMEM>>>(
        (const __half*)pxh, (const __half*)pwq, nullptr, nullptr, pqh, nullptr,
        MTOT, EMB, EMB, 1);
    // 2: latent = xh @ wd^T (f16 out)
    gemm_h_nt<<<dim3(LAT / GBN, MTOT / GBM, 1), 128, GEMM_SMEM>>>(
        (const __half*)pxh, (const __half*)pwd, nullptr, nullptr, plath, nullptr,
        MTOT, LAT, EMB, 1);
    // 3: k,v = lath @ w_up_{k,v}^T (fused via grid.z, f16 out)
    gemm_h_nt<<<dim3(EMB / GBN, MTOT / GBM, 2), 128, GEMM_SMEM>>>(
        (const __half*)plath, (const __half*)pwk, (const __half*)pwv, nullptr,
        pkh, pvh, MTOT, EMB, LAT, 1);
    // 4: causal attention (f16 ctx out)
    flash_attn<<<dim3(SEQ / 64, NHEAD, BATCH), 256, FLASH_SMEM>>>(
        (const __half*)pqh, (const __half*)pkh, (const __half*)pvh,
        (__half*)pctxh, 0);
    // 5: out = ctxh @ wo^T + b_out (fp32 out)
    gemm_h_nt<<<dim3(EMB / GBN, MTOT / GBM, 1), 128, GEMM_SMEM>>>(
        (const __half*)pctxh, (const __half*)pwo, nullptr, b_out, out, nullptr,
        MTOT, EMB, EMB, 0);
}